// round 1
// baseline (speedup 1.0000x reference)
#include <cuda_runtime.h>
#include <cstdint>

#define IMGS 32
#define H 768
#define W 768
#define NPIX (H*W)
#define TILE 64
#define HALO 16
#define REG 96          // TILE + 2*HALO
#define THREADS 512
#define EPS 1e-6f
#define RED_CTAS 64
#define RED_THREADS 256

// scratch: skeleton and radius-accumulator for P (idx 0) and G (idx 1)
__device__ float g_skel[2][IMGS * NPIX];
__device__ float g_acc[2][IMGS * NPIX];
__device__ float g_part[IMGS * RED_CTAS * 4];

__device__ __forceinline__ float4 f4min(float4 a, float4 b) {
    return make_float4(fminf(a.x, b.x), fminf(a.y, b.y), fminf(a.z, b.z), fminf(a.w, b.w));
}
__device__ __forceinline__ float4 f4max(float4 a, float4 b) {
    return make_float4(fmaxf(a.x, b.x), fmaxf(a.y, b.y), fmaxf(a.z, b.z), fmaxf(a.w, b.w));
}
__device__ __forceinline__ float4 maskx(float4 v, int gx) {
    const float NI = __int_as_float(0xff800000);  // -inf
    if ((unsigned)(gx + 0) >= (unsigned)W) v.x = NI;
    if ((unsigned)(gx + 1) >= (unsigned)W) v.y = NI;
    if ((unsigned)(gx + 2) >= (unsigned)W) v.z = NI;
    if ((unsigned)(gx + 3) >= (unsigned)W) v.w = NI;
    return v;
}

// Fused morphology kernel: computes soft_skeleton and 16-step erosion
// accumulator for one 64x64 tile of one (image, tensor).
// grid = (12, 12, 64): z = img*2 + which (0 = pred, 1 = target)
__global__ __launch_bounds__(THREADS, 2)
void morph_kernel(const float* __restrict__ P, const float* __restrict__ G) {
    const int tz = blockIdx.z;
    const int img = tz >> 1;
    const int which = tz & 1;
    const float* __restrict__ src = (which ? G : P) + img * NPIX;

    const int tx0 = blockIdx.x * TILE;
    const int ty0 = blockIdx.y * TILE;
    const int tid = threadIdx.x;

    extern __shared__ float smem[];
    float* A  = smem;                 // current erosion level E_t
    float* Bb = smem + REG * REG;     // scratch (row pass)
    float* Cc = smem + 2 * REG * REG; // next erosion level E_{t+1}

    const float PI_F = __int_as_float(0x7f800000);  // +inf
    const float NI_F = __int_as_float(0xff800000);  // -inf

    // ---- load region (tile + halo), +INF outside image ----
    for (int i = tid; i < REG * REG; i += THREADS) {
        int ly = i / REG;
        int lx = i - ly * REG;
        int gy = ty0 - HALO + ly;
        int gx = tx0 - HALO + lx;
        float v = PI_F;
        if ((unsigned)gx < (unsigned)W && (unsigned)gy < (unsigned)H)
            v = src[gy * W + gx];
        A[ly * REG + lx] = v;
    }
    __syncthreads();

    // per-thread output assignment: 2 adjacent float4 groups of the 64x64 tile
    const int gl0 = tid * 2;            // 1024 groups total (16 per row x 64 rows)
    const int oy0 = gl0 >> 4;           // output row in [0,64)
    const int ogx0 = gl0 & 15;          // even, so both groups are in the same row
    const int oly = HALO + oy0;         // local row
    const int ogrp = (HALO >> 2) + ogx0; // smem float4 group index = 4 + ogx0

    const bool xb = (tx0 == 0) || (tx0 + TILE == W);
    const bool yb = (ty0 == 0) || (ty0 + TILE == H);
    const int gy_out = ty0 + oy0;

    float4 prod0 = make_float4(1.f, 1.f, 1.f, 1.f), prod1 = prod0;
    float4 acc0 = make_float4(0.f, 0.f, 0.f, 0.f), acc1 = acc0;

    for (int t = 0; t < 16; ++t) {
        // ---- pass 1: horizontal min A -> B, rows [t, 96-t) ----
        {
            const int y0 = t, y1 = REG - t;
            const int n = (y1 - y0) * 24;
            for (int i = tid; i < n; i += THREADS) {
                int q = i / 24;
                int g = i - q * 24;
                int y = y0 + q;
                const float4* row = (const float4*)(A + y * REG);
                float4 b = row[g];
                float4 a = row[g > 0 ? g - 1 : g];
                float4 c = row[g < 23 ? g + 1 : g];
                float4 l = make_float4(a.w, b.x, b.y, b.z);
                float4 r = make_float4(b.y, b.z, b.w, c.x);
                ((float4*)(Bb + y * REG))[g] = f4min(f4min(l, b), r);
            }
        }
        __syncthreads();
        // ---- pass 2: vertical min B -> C, rows [t+1, 95-t) ----
        {
            const int y0 = t + 1, y1 = REG - 1 - t;
            const int n = (y1 - y0) * 24;
            for (int i = tid; i < n; i += THREADS) {
                int q = i / 24;
                int g = i - q * 24;
                int y = y0 + q;
                float4 u = ((const float4*)(Bb + (y - 1) * REG))[g];
                float4 m = ((const float4*)(Bb + y * REG))[g];
                float4 d = ((const float4*)(Bb + (y + 1) * REG))[g];
                ((float4*)(Cc + y * REG))[g] = f4min(f4min(u, m), d);
            }
        }
        __syncthreads();

        if (t <= 10) {
            // ---- pass 3: horizontal max C -> B, rows [15, 81), groups [3, 21) ----
            {
                const int n = 66 * 18;
                const int gxbase = tx0 - HALO;
                for (int i = tid; i < n; i += THREADS) {
                    int q = i / 18;
                    int g = 3 + (i - q * 18);
                    int y = 15 + q;
                    const float4* row = (const float4*)(Cc + y * REG);
                    float4 a = row[g - 1];
                    float4 b = row[g];
                    float4 c = row[g + 1];
                    if (xb) {
                        a = maskx(a, gxbase + 4 * (g - 1));
                        b = maskx(b, gxbase + 4 * g);
                        c = maskx(c, gxbase + 4 * (g + 1));
                    }
                    float4 l = make_float4(a.w, b.x, b.y, b.z);
                    float4 r = make_float4(b.y, b.z, b.w, c.x);
                    ((float4*)(Bb + y * REG))[g] = f4max(f4max(l, b), r);
                }
            }
            __syncthreads();
            // ---- pass 4: vertical max + delta + skel update + acc ----
            {
                const float4* rU = (const float4*)(Bb + (oly - 1) * REG);
                const float4* rM = (const float4*)(Bb + oly * REG);
                const float4* rD = (const float4*)(Bb + (oly + 1) * REG);
                float4 u0 = rU[ogrp],     m0 = rM[ogrp],     d0 = rD[ogrp];
                float4 u1 = rU[ogrp + 1], m1 = rM[ogrp + 1], d1 = rD[ogrp + 1];
                if (yb) {
                    if (gy_out - 1 < 0)  { u0 = make_float4(NI_F, NI_F, NI_F, NI_F); u1 = u0; }
                    if (gy_out + 1 >= H) { d0 = make_float4(NI_F, NI_F, NI_F, NI_F); d1 = d0; }
                }
                float4 dil0 = f4max(f4max(u0, m0), d0);
                float4 dil1 = f4max(f4max(u1, m1), d1);
                const float4* rA = (const float4*)(A + oly * REG);
                float4 e0 = rA[ogrp], e1 = rA[ogrp + 1];
                prod0.x *= 1.f - (e0.x - dil0.x);
                prod0.y *= 1.f - (e0.y - dil0.y);
                prod0.z *= 1.f - (e0.z - dil0.z);
                prod0.w *= 1.f - (e0.w - dil0.w);
                prod1.x *= 1.f - (e1.x - dil1.x);
                prod1.y *= 1.f - (e1.y - dil1.y);
                prod1.z *= 1.f - (e1.z - dil1.z);
                prod1.w *= 1.f - (e1.w - dil1.w);
                const float4* rC = (const float4*)(Cc + oly * REG);
                float4 c0 = rC[ogrp], c1 = rC[ogrp + 1];
                acc0.x += c0.x; acc0.y += c0.y; acc0.z += c0.z; acc0.w += c0.w;
                acc1.x += c1.x; acc1.y += c1.y; acc1.z += c1.z; acc1.w += c1.w;
            }
            __syncthreads();
        } else {
            // ---- radius accumulation only (E_{t+1} for t = 11..15) ----
            const float4* rC = (const float4*)(Cc + oly * REG);
            float4 c0 = rC[ogrp], c1 = rC[ogrp + 1];
            acc0.x += c0.x; acc0.y += c0.y; acc0.z += c0.z; acc0.w += c0.w;
            acc1.x += c1.x; acc1.y += c1.y; acc1.z += c1.z; acc1.w += c1.w;
            // no extra sync needed: next pass1 only writes B (last read before
            // the pass-2 sync) and reads C (concurrently read here, no hazard)
        }
        // swap: new E_t lives in C
        float* tmp = A; A = Cc; Cc = tmp;
    }

    // ---- write outputs ----
    float* skelp = g_skel[which] + img * NPIX;
    float* accp  = g_acc[which] + img * NPIX;
    const int gx_out = tx0 + 4 * ogx0;
    const int off = gy_out * W + gx_out;
    float4 s0 = make_float4(1.f - prod0.x, 1.f - prod0.y, 1.f - prod0.z, 1.f - prod0.w);
    float4 s1 = make_float4(1.f - prod1.x, 1.f - prod1.y, 1.f - prod1.z, 1.f - prod1.w);
    ((float4*)(skelp + off))[0] = s0;
    ((float4*)(skelp + off))[1] = s1;
    ((float4*)(accp + off))[0] = acc0;
    ((float4*)(accp + off))[1] = acc1;
}

// Per-image partial sums: a1 = sum(S_P*G*r_G), a2 = sum(S_P*r_G),
//                         b1 = sum(S_G*P*r_P), b2 = sum(S_G*r_P)
__global__ __launch_bounds__(RED_THREADS)
void reduce_kernel(const float* __restrict__ P, const float* __restrict__ G) {
    const int img = blockIdx.y;
    const int base = img * NPIX + blockIdx.x * (NPIX / RED_CTAS);
    const float inv16 = 1.0f / 16.0f;
    float a1 = 0.f, a2 = 0.f, b1 = 0.f, b2 = 0.f;
#pragma unroll
    for (int it = 0; it < 9; ++it) {
        int off = base + (it * RED_THREADS + threadIdx.x) * 4;
        float4 sp = *(const float4*)(&g_skel[0][off]);
        float4 sg = *(const float4*)(&g_skel[1][off]);
        float4 ap = *(const float4*)(&g_acc[0][off]);
        float4 ag = *(const float4*)(&g_acc[1][off]);
        float4 pv = *(const float4*)(&P[off]);
        float4 gv = *(const float4*)(&G[off]);
#define ACCUM(c) { \
        float rg = ag.c * inv16 * gv.c + EPS; \
        float rp = ap.c * inv16 * pv.c + EPS; \
        a1 += sp.c * gv.c * rg; a2 += sp.c * rg; \
        b1 += sg.c * pv.c * rp; b2 += sg.c * rp; }
        ACCUM(x) ACCUM(y) ACCUM(z) ACCUM(w)
#undef ACCUM
    }
#pragma unroll
    for (int o = 16; o; o >>= 1) {
        a1 += __shfl_down_sync(0xffffffffu, a1, o);
        a2 += __shfl_down_sync(0xffffffffu, a2, o);
        b1 += __shfl_down_sync(0xffffffffu, b1, o);
        b2 += __shfl_down_sync(0xffffffffu, b2, o);
    }
    __shared__ float sm[8][4];
    const int lane = threadIdx.x & 31, wrp = threadIdx.x >> 5;
    if (lane == 0) { sm[wrp][0] = a1; sm[wrp][1] = a2; sm[wrp][2] = b1; sm[wrp][3] = b2; }
    __syncthreads();
    if (threadIdx.x < 4) {
        float s = 0.f;
#pragma unroll
        for (int ww = 0; ww < 8; ++ww) s += sm[ww][threadIdx.x];
        g_part[(img * RED_CTAS + blockIdx.x) * 4 + threadIdx.x] = s;
    }
}

__global__ void final_kernel(float* __restrict__ out) {
    __shared__ float sums[IMGS][4];
    const int tid = threadIdx.x;
    if (tid < IMGS * 4) {
        int img = tid >> 2, k = tid & 3;
        float s = 0.f;
        for (int c = 0; c < RED_CTAS; ++c)
            s += g_part[(img * RED_CTAS + c) * 4 + k];
        sums[img][k] = s;
    }
    __syncthreads();
    if (tid == 0) {
        float loss = 0.f;
        for (int i = 0; i < IMGS; ++i) {
            float prec = sums[i][0] / (sums[i][1] + EPS);
            float rec  = sums[i][2] / (sums[i][3] + EPS);
            float cbd  = 2.f * prec * rec / (prec + rec + EPS);
            loss += 1.f - cbd;
        }
        out[0] = loss / (float)IMGS;
    }
}

extern "C" void kernel_launch(void* const* d_in, const int* in_sizes, int n_in,
                              void* d_out, int out_size) {
    const float* P = (const float*)d_in[0];   // pred
    const float* G = (const float*)d_in[1];   // target
    const size_t smem_bytes = 3u * REG * REG * sizeof(float);  // 110592
    cudaFuncSetAttribute(morph_kernel, cudaFuncAttributeMaxDynamicSharedMemorySize,
                         (int)smem_bytes);
    dim3 grid(W / TILE, H / TILE, IMGS * 2);
    morph_kernel<<<grid, THREADS, smem_bytes>>>(P, G);
    reduce_kernel<<<dim3(RED_CTAS, IMGS), RED_THREADS>>>(P, G);
    final_kernel<<<1, 128>>>((float*)d_out);
}

// round 4
// speedup vs baseline: 2.2991x; 2.2991x over previous
#include <cuda_runtime.h>
#include <cstdint>

#define IMGS 32
#define H 768
#define W 768
#define NPIX (H*W)
#define TW 96            // output tile width
#define TH 64            // output tile height
#define RROWS 96         // region rows
#define RWF 128          // region width (floats) = 32 lanes x float4
#define WARPS 24
#define THREADS (WARPS*32)
#define ROWS_PW 4        // rows per warp
#define EPS 1e-6f
#define RED_CTAS 64
#define RED_THREADS 256

__device__ float g_skel[2][IMGS * NPIX];
__device__ float g_acc[2][IMGS * NPIX];
__device__ float g_part[IMGS * RED_CTAS * 4];

__device__ __forceinline__ float4 f4min(float4 a, float4 b) {
    return make_float4(fminf(a.x, b.x), fminf(a.y, b.y), fminf(a.z, b.z), fminf(a.w, b.w));
}
__device__ __forceinline__ float4 f4max(float4 a, float4 b) {
    return make_float4(fmaxf(a.x, b.x), fmaxf(a.y, b.y), fmaxf(a.z, b.z), fmaxf(a.w, b.w));
}

// horizontal 3-window min/max across the 128-wide row (one warp = one row).
// lane-edge clamp (shfl returns own value) only corrupts the invalid ring.
__device__ __forceinline__ float4 hmin3(float4 b) {
    float lw = __shfl_up_sync(0xffffffffu, b.w, 1);
    float rx = __shfl_down_sync(0xffffffffu, b.x, 1);
    float4 r;
    r.x = fminf(fminf(lw, b.x), b.y);
    r.y = fminf(fminf(b.x, b.y), b.z);
    r.z = fminf(fminf(b.y, b.z), b.w);
    r.w = fminf(fminf(b.z, b.w), rx);
    return r;
}
__device__ __forceinline__ float4 hmax3(float4 b) {
    float lw = __shfl_up_sync(0xffffffffu, b.w, 1);
    float rx = __shfl_down_sync(0xffffffffu, b.x, 1);
    float4 r;
    r.x = fmaxf(fmaxf(lw, b.x), b.y);
    r.y = fmaxf(fmaxf(b.x, b.y), b.z);
    r.z = fmaxf(fmaxf(b.y, b.z), b.w);
    r.w = fmaxf(fmaxf(b.z, b.w), rx);
    return r;
}

__device__ __forceinline__ float4 ldrow(const float* B, int r, int lane) {
    return *(const float4*)(B + r * RWF + 4 * lane);
}
__device__ __forceinline__ void strow(float* B, int r, int lane, float4 v) {
    *(float4*)(B + r * RWF + 4 * lane) = v;
}

// Fused morphology. Each warp owns 4 region rows. State buffers ping-pong in
// smem; horizontal windows via shuffles; one __syncthreads per iteration.
// grid = (8, 12, 64): z = img*2 + which (0 = pred, 1 = target)
__global__ __launch_bounds__(THREADS, 1)
void morph_kernel(const float* __restrict__ P, const float* __restrict__ Gt) {
    const int tz = blockIdx.z;
    const int img = tz >> 1;
    const int which = tz & 1;
    const float* __restrict__ src = (which ? Gt : P) + img * NPIX;

    const int tx0 = blockIdx.x * TW;
    const int ty0 = blockIdx.y * TH;
    const int tid = threadIdx.x;
    const int lane = tid & 31;
    const int w = tid >> 5;
    const int r0 = ROWS_PW * w;

    extern __shared__ float smem[];
    float* X = smem;                    // current erosion level E_t
    float* Y = smem + RROWS * RWF;      // next level E_{t+1}

    const float PI_F = __int_as_float(0x7f800000);   // +inf
    const float NI_F = __int_as_float(0xff800000);   // -inf
    const float4 NEG4 = make_float4(NI_F, NI_F, NI_F, NI_F);

    // ---- load region: rows ty0-16+y, cols tx0-16+4g; +inf outside image ----
#pragma unroll
    for (int i = tid; i < RROWS * 32; i += THREADS) {
        int y = i >> 5, g = i & 31;
        int gy = ty0 - 16 + y;
        int gx = tx0 - 16 + 4 * g;
        float4 val = make_float4(PI_F, PI_F, PI_F, PI_F);
        if ((unsigned)gy < (unsigned)H && (unsigned)gx < (unsigned)W)
            val = *(const float4*)(src + gy * W + gx);
        strow(X, y, g, val);
    }
    __syncthreads();

    const bool outw = (w >= 4 && w <= 19);   // strip within output rows 16..79
    const bool xout = (tx0 == 0 && lane < 4) || (tx0 + TW == W && lane >= 28);
    const bool topm = (w == 4) && (ty0 == 0);
    const bool botm = (w == 19) && (ty0 + TH == H);
    const int ru = (r0 == 0) ? 0 : r0 - 1;                   // clamped
    const int rd = (r0 + ROWS_PW >= RROWS) ? RROWS - 1 : r0 + ROWS_PW;

    float4 prod[ROWS_PW], acc[ROWS_PW];
#pragma unroll
    for (int v = 0; v < ROWS_PW; ++v) {
        prod[v] = make_float4(1.f, 1.f, 1.f, 1.f);
        acc[v] = make_float4(0.f, 0.f, 0.f, 0.f);
    }

#pragma unroll 1
    for (int t = 0; t < 16; ++t) {
        // ---- erode X -> Y on own rows (vertical rolling, horizontal shfl) ----
        float4 e[ROWS_PW];
        {
            float4 hp = hmin3(ldrow(X, ru, lane));
            float4 hc = hmin3(ldrow(X, r0, lane));
#pragma unroll
            for (int v = 0; v < ROWS_PW; ++v) {
                float4 raw = ldrow(X, (v < ROWS_PW - 1) ? r0 + v + 1 : rd, lane);
                float4 hn = hmin3(raw);
                e[v] = f4min(f4min(hp, hc), hn);
                strow(Y, r0 + v, lane, e[v]);
                hp = hc; hc = hn;
            }
        }
        __syncthreads();

        if (outw) {
#pragma unroll
            for (int v = 0; v < ROWS_PW; ++v) {
                acc[v].x += e[v].x; acc[v].y += e[v].y;
                acc[v].z += e[v].z; acc[v].w += e[v].w;
            }
            if (t <= 10) {
                // dilate(E_{t+1}) with -inf outside the image; delta vs E_t (in X)
                float4 up = topm ? NEG4 : (xout ? NEG4 : ldrow(Y, r0 - 1, lane));
                float4 dn = botm ? NEG4 : (xout ? NEG4 : ldrow(Y, r0 + ROWS_PW, lane));
                float4 hxp = hmax3(up);
                float4 hxc = hmax3(xout ? NEG4 : e[0]);
#pragma unroll
                for (int v = 0; v < ROWS_PW; ++v) {
                    float4 hxn = (v < ROWS_PW - 1) ? hmax3(xout ? NEG4 : e[v + 1])
                                                   : hmax3(dn);
                    float4 d = f4max(f4max(hxp, hxc), hxn);
                    float4 in = ldrow(X, r0 + v, lane);   // E_t, own row (no race)
                    // prod *= 1 - (in - d)  ==  prod += prod * (d - in)
                    prod[v].x = fmaf(prod[v].x, d.x - in.x, prod[v].x);
                    prod[v].y = fmaf(prod[v].y, d.y - in.y, prod[v].y);
                    prod[v].z = fmaf(prod[v].z, d.z - in.z, prod[v].z);
                    prod[v].w = fmaf(prod[v].w, d.w - in.w, prod[v].w);
                    hxp = hxc; hxc = hxn;
                }
            }
        }
        // swap buffers; no extra sync needed (row ownership keeps writes disjoint
        // from any cross-warp reads, see analysis)
        float* tmp = X; X = Y; Y = tmp;
    }

    // ---- write outputs (output rows 16..79 => warps 4..19; cols lanes 4..27) ----
    if (outw && lane >= 4 && lane < 28) {
        float* skelp = g_skel[which] + img * NPIX;
        float* accp  = g_acc[which] + img * NPIX;
        const int gxo = tx0 + 4 * (lane - 4);
        const int gy0 = ty0 + (r0 - 16);
#pragma unroll
        for (int v = 0; v < ROWS_PW; ++v) {
            const int off = (gy0 + v) * W + gxo;
            float4 s = make_float4(1.f - prod[v].x, 1.f - prod[v].y,
                                   1.f - prod[v].z, 1.f - prod[v].w);
            *(float4*)(skelp + off) = s;
            *(float4*)(accp + off) = acc[v];
        }
    }
}

// Per-image partial sums: a1 = sum(S_P*G*r_G), a2 = sum(S_P*r_G),
//                         b1 = sum(S_G*P*r_P), b2 = sum(S_G*r_P)
__global__ __launch_bounds__(RED_THREADS)
void reduce_kernel(const float* __restrict__ P, const float* __restrict__ G) {
    const int img = blockIdx.y;
    const int base = img * NPIX + blockIdx.x * (NPIX / RED_CTAS);
    const float inv16 = 1.0f / 16.0f;
    float a1 = 0.f, a2 = 0.f, b1 = 0.f, b2 = 0.f;
#pragma unroll
    for (int it = 0; it < 9; ++it) {
        int off = base + (it * RED_THREADS + threadIdx.x) * 4;
        float4 sp = *(const float4*)(&g_skel[0][off]);
        float4 sg = *(const float4*)(&g_skel[1][off]);
        float4 ap = *(const float4*)(&g_acc[0][off]);
        float4 ag = *(const float4*)(&g_acc[1][off]);
        float4 pv = *(const float4*)(&P[off]);
        float4 gv = *(const float4*)(&G[off]);
#define ACCUM(c) { \
        float rg = ag.c * inv16 * gv.c + EPS; \
        float rp = ap.c * inv16 * pv.c + EPS; \
        a1 += sp.c * gv.c * rg; a2 += sp.c * rg; \
        b1 += sg.c * pv.c * rp; b2 += sg.c * rp; }
        ACCUM(x) ACCUM(y) ACCUM(z) ACCUM(w)
#undef ACCUM
    }
#pragma unroll
    for (int o = 16; o; o >>= 1) {
        a1 += __shfl_down_sync(0xffffffffu, a1, o);
        a2 += __shfl_down_sync(0xffffffffu, a2, o);
        b1 += __shfl_down_sync(0xffffffffu, b1, o);
        b2 += __shfl_down_sync(0xffffffffu, b2, o);
    }
    __shared__ float sm[8][4];
    const int lane = threadIdx.x & 31, wrp = threadIdx.x >> 5;
    if (lane == 0) { sm[wrp][0] = a1; sm[wrp][1] = a2; sm[wrp][2] = b1; sm[wrp][3] = b2; }
    __syncthreads();
    if (threadIdx.x < 4) {
        float s = 0.f;
#pragma unroll
        for (int ww = 0; ww < 8; ++ww) s += sm[ww][threadIdx.x];
        g_part[(img * RED_CTAS + blockIdx.x) * 4 + threadIdx.x] = s;
    }
}

__global__ void final_kernel(float* __restrict__ out) {
    __shared__ float sums[IMGS][4];
    const int tid = threadIdx.x;
    if (tid < IMGS * 4) {
        int img = tid >> 2, k = tid & 3;
        float s = 0.f;
        for (int c = 0; c < RED_CTAS; ++c)
            s += g_part[(img * RED_CTAS + c) * 4 + k];
        sums[img][k] = s;
    }
    __syncthreads();
    if (tid == 0) {
        float loss = 0.f;
        for (int i = 0; i < IMGS; ++i) {
            float prec = sums[i][0] / (sums[i][1] + EPS);
            float rec  = sums[i][2] / (sums[i][3] + EPS);
            float cbd  = 2.f * prec * rec / (prec + rec + EPS);
            loss += 1.f - cbd;
        }
        out[0] = loss / (float)IMGS;
    }
}

extern "C" void kernel_launch(void* const* d_in, const int* in_sizes, int n_in,
                              void* d_out, int out_size) {
    const float* P = (const float*)d_in[0];   // pred
    const float* G = (const float*)d_in[1];   // target
    const size_t smem_bytes = 2u * RROWS * RWF * sizeof(float);  // 98304
    cudaFuncSetAttribute(morph_kernel, cudaFuncAttributeMaxDynamicSharedMemorySize,
                         (int)smem_bytes);
    dim3 grid(W / TW, H / TH, IMGS * 2);
    morph_kernel<<<grid, THREADS, smem_bytes>>>(P, G);
    reduce_kernel<<<dim3(RED_CTAS, IMGS), RED_THREADS>>>(P, G);
    final_kernel<<<1, 128>>>((float*)d_out);
}

// round 5
// speedup vs baseline: 3.1965x; 1.3903x over previous
#include <cuda_runtime.h>
#include <cstdint>

#define IMGS 32
#define H 768
#define W 768
#define NPIX (H*W)
#define TW 96            // output tile width
#define TH 64            // output tile height
#define RROWS 96         // region rows
#define WARPS 16
#define THREADS (WARPS*32)
#define ROWS_PW 6        // region rows per warp
#define EPS 1e-6f
#define RED_CTAS 64
#define RED_THREADS 256

__device__ float g_skel[2][IMGS * NPIX];
__device__ float g_acc[2][IMGS * NPIX];
__device__ float g_part[IMGS * RED_CTAS * 4];

__device__ __forceinline__ float4 f4min(float4 a, float4 b) {
    return make_float4(fminf(a.x, b.x), fminf(a.y, b.y), fminf(a.z, b.z), fminf(a.w, b.w));
}
__device__ __forceinline__ float4 f4max(float4 a, float4 b) {
    return make_float4(fmaxf(a.x, b.x), fmaxf(a.y, b.y), fmaxf(a.z, b.z), fmaxf(a.w, b.w));
}

// horizontal 3-window min/max across the 128-wide row (one warp = one row).
// lane-edge clamp (shfl returns own value) only corrupts the invalid ring.
__device__ __forceinline__ float4 hmin3(float4 b) {
    float lw = __shfl_up_sync(0xffffffffu, b.w, 1);
    float rx = __shfl_down_sync(0xffffffffu, b.x, 1);
    float4 r;
    r.x = fminf(fminf(lw, b.x), b.y);
    r.y = fminf(fminf(b.x, b.y), b.z);
    r.z = fminf(fminf(b.y, b.z), b.w);
    r.w = fminf(fminf(b.z, b.w), rx);
    return r;
}
__device__ __forceinline__ float4 hmax3(float4 b) {
    float lw = __shfl_up_sync(0xffffffffu, b.w, 1);
    float rx = __shfl_down_sync(0xffffffffu, b.x, 1);
    float4 r;
    r.x = fmaxf(fmaxf(lw, b.x), b.y);
    r.y = fmaxf(fmaxf(b.x, b.y), b.z);
    r.z = fmaxf(fmaxf(b.y, b.z), b.w);
    r.w = fmaxf(fmaxf(b.z, b.w), rx);
    return r;
}

__shared__ __device__ float4 g_dummy;  // (unused; keeps nvcc happy on some toolchains)

struct Ctx {
    int w, lane, r0;
    bool outw, xout, t0, b0;
};

// one iteration: erode in[] -> out[] (regs; boundary rows via smem), then
// dilate+skel+acc.  PAR = t&1 selects the boundary ping-pong buffer.
template <int PAR>
__device__ __forceinline__ void step_it(
    int t, const Ctx& cx,
    float4 (&in)[ROWS_PW], float4 (&out)[ROWS_PW],
    float4 (&prod)[ROWS_PW], float4 (&acc)[ROWS_PW],
    float4 (*bnd)[WARPS][2][32])
{
    const float NI_F = __int_as_float(0xff800000);
    const float4 NEG4 = make_float4(NI_F, NI_F, NI_F, NI_F);
    const int w = cx.w, lane = cx.lane;

    // ---- erosion: own rows in registers, neighbor boundary rows via smem ----
    {
        float4 up   = (w > 0)         ? bnd[PAR][w - 1][1][lane] : in[0];
        float4 down = (w < WARPS - 1) ? bnd[PAR][w + 1][0][lane] : in[ROWS_PW - 1];
        float4 hp = hmin3(up);
        float4 hc = hmin3(in[0]);
#pragma unroll
        for (int v = 0; v < ROWS_PW; ++v) {
            float4 hn = hmin3(v < ROWS_PW - 1 ? in[v + 1] : down);
            out[v] = f4min(f4min(hp, hc), hn);
            hp = hc; hc = hn;
        }
        bnd[PAR ^ 1][w][0][lane] = out[0];
        bnd[PAR ^ 1][w][1][lane] = out[ROWS_PW - 1];
    }
    __syncthreads();

#pragma unroll
    for (int v = 0; v < ROWS_PW; ++v) {
        acc[v].x += out[v].x; acc[v].y += out[v].y;
        acc[v].z += out[v].z; acc[v].w += out[v].w;
    }
    if (cx.outw && t <= 10) {
        // rows r0-1 .. r0+6 of E_{t+1}; mask rows outside the image with -inf
        // (a masked row is masked for every window position -> mask, then roll)
        float4 bu = bnd[PAR ^ 1][w - 1][1][lane];
        float4 bd = bnd[PAR ^ 1][w + 1][0][lane];
        const int r0 = cx.r0;
        auto m = [&](int r, float4 v) -> float4 {
            bool neg = cx.xout | (cx.t0 & (r < 16)) | (cx.b0 & (r > 79));
            return neg ? NEG4 : v;
        };
        float4 hxp = hmax3(m(r0 - 1, bu));
        float4 hxc = hmax3(m(r0, out[0]));
#pragma unroll
        for (int v = 0; v < ROWS_PW; ++v) {
            float4 hxn = hmax3(m(r0 + v + 1, v < ROWS_PW - 1 ? out[v + 1] : bd));
            float4 d = f4max(f4max(hxp, hxc), hxn);
            // prod *= 1 - (in - d)  ==  prod += prod * (d - in)
            prod[v].x = fmaf(prod[v].x, d.x - in[v].x, prod[v].x);
            prod[v].y = fmaf(prod[v].y, d.y - in[v].y, prod[v].y);
            prod[v].z = fmaf(prod[v].z, d.z - in[v].z, prod[v].z);
            prod[v].w = fmaf(prod[v].w, d.w - in[v].w, prod[v].w);
            hxp = hxc; hxc = hxn;
        }
    }
}

// Fused morphology: each warp keeps a 6-row strip of the erosion state in
// registers; smem holds only per-warp top/bottom boundary rows (ping-pong).
// grid = (8, 12, 64): z = img*2 + which (0 = pred, 1 = target)
__global__ __launch_bounds__(THREADS, 1)
void morph_kernel(const float* __restrict__ P, const float* __restrict__ Gt) {
    const int tz = blockIdx.z;
    const int img = tz >> 1;
    const int which = tz & 1;
    const float* __restrict__ src = (which ? Gt : P) + img * NPIX;

    const int tx0 = blockIdx.x * TW;
    const int ty0 = blockIdx.y * TH;
    const int tid = threadIdx.x;
    const int lane = tid & 31;
    const int w = tid >> 5;
    const int r0 = ROWS_PW * w;
    const int gx0 = tx0 - 16 + 4 * lane;

    __shared__ float4 bnd[2][WARPS][2][32];   // [buf][warp][top/bot][lane]

    const float PI_F = __int_as_float(0x7f800000);   // +inf

    float4 cur[ROWS_PW], nxt[ROWS_PW], prod[ROWS_PW], acc[ROWS_PW];

    // ---- load E_0 strip: rows ty0-16+r0+v, cols gx0..gx0+3; +inf outside ----
#pragma unroll
    for (int v = 0; v < ROWS_PW; ++v) {
        int gy = ty0 - 16 + r0 + v;
        float4 val = make_float4(PI_F, PI_F, PI_F, PI_F);
        if ((unsigned)gy < (unsigned)H && (unsigned)gx0 < (unsigned)W)
            val = *(const float4*)(src + gy * W + gx0);
        cur[v] = val;
        prod[v] = make_float4(1.f, 1.f, 1.f, 1.f);
        acc[v] = make_float4(0.f, 0.f, 0.f, 0.f);
    }
    bnd[0][w][0][lane] = cur[0];
    bnd[0][w][1][lane] = cur[ROWS_PW - 1];
    __syncthreads();

    Ctx cx;
    cx.w = w; cx.lane = lane; cx.r0 = r0;
    cx.outw = (w >= 2 && w <= 13);       // strips overlapping output rows 16..79
    cx.xout = (tx0 == 0 && lane < 4) || (tx0 + TW == W && lane >= 28);
    cx.t0 = (ty0 == 0);
    cx.b0 = (ty0 + TH == H);

#pragma unroll 1
    for (int t = 0; t < 16; t += 2) {
        step_it<0>(t,     cx, cur, nxt, prod, acc, bnd);
        step_it<1>(t + 1, cx, nxt, cur, prod, acc, bnd);
    }

    // ---- write outputs: region rows 16..79, cols = lanes 4..27 ----
    if (cx.outw && lane >= 4 && lane < 28) {
        float* skelp = g_skel[which] + img * NPIX;
        float* accp  = g_acc[which] + img * NPIX;
        const int gxo = tx0 + 4 * (lane - 4);
#pragma unroll
        for (int v = 0; v < ROWS_PW; ++v) {
            const int r = r0 + v;
            if (r >= 16 && r < 80) {
                const int off = (ty0 + r - 16) * W + gxo;
                float4 s = make_float4(1.f - prod[v].x, 1.f - prod[v].y,
                                       1.f - prod[v].z, 1.f - prod[v].w);
                *(float4*)(skelp + off) = s;
                *(float4*)(accp + off) = acc[v];
            }
        }
    }
}

// Per-image partial sums: a1 = sum(S_P*G*r_G), a2 = sum(S_P*r_G),
//                         b1 = sum(S_G*P*r_P), b2 = sum(S_G*r_P)
__global__ __launch_bounds__(RED_THREADS)
void reduce_kernel(const float* __restrict__ P, const float* __restrict__ G) {
    const int img = blockIdx.y;
    const int base = img * NPIX + blockIdx.x * (NPIX / RED_CTAS);
    const float inv16 = 1.0f / 16.0f;
    float a1 = 0.f, a2 = 0.f, b1 = 0.f, b2 = 0.f;
#pragma unroll
    for (int it = 0; it < 9; ++it) {
        int off = base + (it * RED_THREADS + threadIdx.x) * 4;
        float4 sp = *(const float4*)(&g_skel[0][off]);
        float4 sg = *(const float4*)(&g_skel[1][off]);
        float4 ap = *(const float4*)(&g_acc[0][off]);
        float4 ag = *(const float4*)(&g_acc[1][off]);
        float4 pv = *(const float4*)(&P[off]);
        float4 gv = *(const float4*)(&G[off]);
#define ACCUM(c) { \
        float rg = ag.c * inv16 * gv.c + EPS; \
        float rp = ap.c * inv16 * pv.c + EPS; \
        a1 += sp.c * gv.c * rg; a2 += sp.c * rg; \
        b1 += sg.c * pv.c * rp; b2 += sg.c * rp; }
        ACCUM(x) ACCUM(y) ACCUM(z) ACCUM(w)
#undef ACCUM
    }
#pragma unroll
    for (int o = 16; o; o >>= 1) {
        a1 += __shfl_down_sync(0xffffffffu, a1, o);
        a2 += __shfl_down_sync(0xffffffffu, a2, o);
        b1 += __shfl_down_sync(0xffffffffu, b1, o);
        b2 += __shfl_down_sync(0xffffffffu, b2, o);
    }
    __shared__ float sm[8][4];
    const int lane = threadIdx.x & 31, wrp = threadIdx.x >> 5;
    if (lane == 0) { sm[wrp][0] = a1; sm[wrp][1] = a2; sm[wrp][2] = b1; sm[wrp][3] = b2; }
    __syncthreads();
    if (threadIdx.x < 4) {
        float s = 0.f;
#pragma unroll
        for (int ww = 0; ww < 8; ++ww) s += sm[ww][threadIdx.x];
        g_part[(img * RED_CTAS + blockIdx.x) * 4 + threadIdx.x] = s;
    }
}

__global__ void final_kernel(float* __restrict__ out) {
    __shared__ float sums[IMGS][4];
    const int tid = threadIdx.x;
    if (tid < IMGS * 4) {
        int img = tid >> 2, k = tid & 3;
        float s = 0.f;
        for (int c = 0; c < RED_CTAS; ++c)
            s += g_part[(img * RED_CTAS + c) * 4 + k];
        sums[img][k] = s;
    }
    __syncthreads();
    if (tid == 0) {
        float loss = 0.f;
        for (int i = 0; i < IMGS; ++i) {
            float prec = sums[i][0] / (sums[i][1] + EPS);
            float rec  = sums[i][2] / (sums[i][3] + EPS);
            float cbd  = 2.f * prec * rec / (prec + rec + EPS);
            loss += 1.f - cbd;
        }
        out[0] = loss / (float)IMGS;
    }
}

extern "C" void kernel_launch(void* const* d_in, const int* in_sizes, int n_in,
                              void* d_out, int out_size) {
    const float* P = (const float*)d_in[0];   // pred
    const float* G = (const float*)d_in[1];   // target
    dim3 grid(W / TW, H / TH, IMGS * 2);
    morph_kernel<<<grid, THREADS>>>(P, G);
    reduce_kernel<<<dim3(RED_CTAS, IMGS), RED_THREADS>>>(P, G);
    final_kernel<<<1, 128>>>((float*)d_out);
}